// round 6
// baseline (speedup 1.0000x reference)
#include <cuda_runtime.h>

// Shift_14422500180434: 3x3 spatial shift "im2col-lite".
//   x:   [32, 64, 56, 56] f32 -> out: [32, 576, 56, 56] f32
//   out[n, c*9 + 3*dy + dx, h, w] = x[n, c, h+dy-1, w+dx-1] (zero pad)
//
// R6: R2 structure (best: 39.0us) with 256-bit global accesses (sm_100+).
// One thread = (n, c, h, group-of-8 w). Per dy: one LDG.256 + <=2 edge
// scalars -> three STG.256 (streaming). Halves store instruction count and
// L1 store wavefronts; 1KB contiguous per warp-store per plane.

#define N_ 32
#define C_ 64
#define H_ 56
#define W_ 56
#define W8_ 7               // W/8
#define PLANE_ 3136         // 56*56
#define TOTAL_THREADS_ (N_ * C_ * H_ * W8_)   // 802,816 = 3136 * 256

__device__ __forceinline__ void ld256_nc(const float* p, float* v) {
    asm volatile("ld.global.nc.v8.f32 {%0,%1,%2,%3,%4,%5,%6,%7}, [%8];"
                 : "=f"(v[0]), "=f"(v[1]), "=f"(v[2]), "=f"(v[3]),
                   "=f"(v[4]), "=f"(v[5]), "=f"(v[6]), "=f"(v[7])
                 : "l"(p));
}

__device__ __forceinline__ void st256_cs(float* p, const float* v) {
    asm volatile("st.global.cs.v8.f32 [%0], {%1,%2,%3,%4,%5,%6,%7,%8};"
                 :: "l"(p), "f"(v[0]), "f"(v[1]), "f"(v[2]), "f"(v[3]),
                    "f"(v[4]), "f"(v[5]), "f"(v[6]), "f"(v[7])
                 : "memory");
}

__global__ __launch_bounds__(256) void shift_kernel(
    const float* __restrict__ x, float* __restrict__ out)
{
    int t = blockIdx.x * blockDim.x + threadIdx.x;

    int w8 = t % W8_;
    int h  = (t / W8_) % H_;
    int c  = (t / (W8_ * H_)) % C_;
    int n  = t / (W8_ * H_ * C_);
    int w0 = w8 * 8;

    const float* __restrict__ xp = x + ((n * C_ + c) * H_) * (long)W_ + w0;

    // Output base for shift s=0 at (n, c, h, w0); planes PLANE_ apart.
    float* __restrict__ op =
        out + (((long)(n * (C_ * 9) + c * 9)) * H_ + h) * W_ + w0;

#pragma unroll
    for (int dy = 0; dy < 3; ++dy) {
        int hh = h + dy - 1;
        bool hv = ((unsigned)hh < (unsigned)H_);

        // m[j]: input float at (hh, w0 + j - 1), j = 0..9 (0 outside).
        float m[10];
#pragma unroll
        for (int j = 0; j < 10; ++j) m[j] = 0.f;
        if (hv) {
            const float* rp = xp + hh * W_;
            ld256_nc(rp, m + 1);                    // m[1..8] = row[w0..w0+7]
            if (w8 > 0)       m[0] = rp[-1];
            if (w8 < W8_ - 1) m[9] = rp[8];
        }

        float* o = op + (long)(dy * 3) * PLANE_;
        st256_cs(o,              m + 0);            // dx=0
        st256_cs(o + PLANE_,     m + 1);            // dx=1
        st256_cs(o + 2 * PLANE_, m + 2);            // dx=2
    }
}

extern "C" void kernel_launch(void* const* d_in, const int* in_sizes, int n_in,
                              void* d_out, int out_size)
{
    const float* x = (const float*)d_in[0];
    float* out = (float*)d_out;
    const int threads = 256;
    const int blocks = TOTAL_THREADS_ / threads;  // 3136, exact
    shift_kernel<<<blocks, threads>>>(x, out);
}

// round 7
// speedup vs baseline: 1.1084x; 1.1084x over previous
#include <cuda_runtime.h>

// Shift_14422500180434: 3x3 spatial shift "im2col-lite".
//   x:   [N=32, C=64, H=56, W=56] f32
//   out: [N=32, C*9=576, H=56, W=56] f32
//   out[n, c*9 + 3*dy + dx, h, w] = x[n, c, h+dy-1, w+dx-1]  (zero pad)
//
// R7 = R2 (best measured: 39.0us), re-landed after R3-R6 experiments showed
// every restructure (smem staging, h-pairing, STG.256) is neutral/worse:
// the kernel sits at the DRAM write-bandwidth wall (231MB stores + 25.7MB
// reads at ~6TB/s sustained).
//  - __stcs streaming stores: output is write-once, keep it out of L2's way.
//  - per-dy row streaming: 6 live row floats -> 25 regs, occ ~80%.
//  - exact grid (6272*256 == total threads): no bounds guard.

#define N_ 32
#define C_ 64
#define H_ 56
#define W_ 56
#define W4_ 14              // W/4
#define PLANE_ (H_ * W_)    // 3136
#define TOTAL_THREADS_ (N_ * C_ * H_ * W4_)   // 1,605,632 = 6272 * 256

__global__ __launch_bounds__(256) void shift_kernel(
    const float* __restrict__ x, float* __restrict__ out)
{
    int t = blockIdx.x * blockDim.x + threadIdx.x;

    int w4 = t % W4_;
    int h  = (t / W4_) % H_;
    int c  = (t / (W4_ * H_)) % C_;
    int n  = t / (W4_ * H_ * C_);
    int w0 = w4 * 4;

    const float* __restrict__ xp = x + ((n * C_ + c) * H_) * (long)W_ + w0;

    // Output base for shift s=0 at this (n, c, h, w0); planes are PLANE_ apart.
    float* __restrict__ op =
        out + (((long)(n * (C_ * 9) + c * 9)) * H_ + h) * W_ + w0;

#pragma unroll
    for (int dy = 0; dy < 3; ++dy) {
        int hh = h + dy - 1;
        bool hv = ((unsigned)hh < (unsigned)H_);

        // row[j]: input float at (hh, w0 + j - 1), j = 0..5 (zero outside)
        float4 v = make_float4(0.f, 0.f, 0.f, 0.f);
        float left = 0.f, right = 0.f;
        if (hv) {
            const float* rp = xp + hh * W_;
            v = *reinterpret_cast<const float4*>(rp);
            if (w4 > 0)       left  = rp[-1];
            if (w4 < W4_ - 1) right = rp[4];
        }
        float r0 = left, r1 = v.x, r2 = v.y, r3 = v.z, r4 = v.w, r5 = right;

        float* o = op + (long)(dy * 3) * PLANE_;
        __stcs(reinterpret_cast<float4*>(o),
               make_float4(r0, r1, r2, r3));
        __stcs(reinterpret_cast<float4*>(o + PLANE_),
               make_float4(r1, r2, r3, r4));
        __stcs(reinterpret_cast<float4*>(o + 2 * PLANE_),
               make_float4(r2, r3, r4, r5));
    }
}

extern "C" void kernel_launch(void* const* d_in, const int* in_sizes, int n_in,
                              void* d_out, int out_size)
{
    const float* x = (const float*)d_in[0];
    float* out = (float*)d_out;
    const int threads = 256;
    const int blocks = TOTAL_THREADS_ / threads;  // 6272, exact
    shift_kernel<<<blocks, threads>>>(x, out);
}

// round 8
// speedup vs baseline: 1.1166x; 1.0074x over previous
#include <cuda_runtime.h>

// Shift_14422500180434: 3x3 spatial shift "im2col-lite".
//   x:   [N=32, C=64, H=56, W=56] f32
//   out: [N=32, C*9=576, H=56, W=56] f32
//   out[n, c*9 + 3*dy + dx, h, w] = x[n, c, h+dy-1, w+dx-1]  (zero pad)
//
// R8 = R2/R7 (best measured: 39.0us, reproducible DRAM-write floor) with
// block=512: 8KB contiguous store bursts per plane per block instead of 4KB.
// Same instruction stream, same 25 regs, exact grid (3136*512).
//  - __stcs streaming stores: output is write-once.
//  - per-dy row streaming: 6 live row floats.

#define N_ 32
#define C_ 64
#define H_ 56
#define W_ 56
#define W4_ 14              // W/4
#define PLANE_ (H_ * W_)    // 3136
#define TOTAL_THREADS_ (N_ * C_ * H_ * W4_)   // 1,605,632 = 3136 * 512

__global__ __launch_bounds__(512) void shift_kernel(
    const float* __restrict__ x, float* __restrict__ out)
{
    int t = blockIdx.x * blockDim.x + threadIdx.x;

    int w4 = t % W4_;
    int h  = (t / W4_) % H_;
    int c  = (t / (W4_ * H_)) % C_;
    int n  = t / (W4_ * H_ * C_);
    int w0 = w4 * 4;

    const float* __restrict__ xp = x + ((n * C_ + c) * H_) * (long)W_ + w0;

    // Output base for shift s=0 at this (n, c, h, w0); planes are PLANE_ apart.
    float* __restrict__ op =
        out + (((long)(n * (C_ * 9) + c * 9)) * H_ + h) * W_ + w0;

#pragma unroll
    for (int dy = 0; dy < 3; ++dy) {
        int hh = h + dy - 1;
        bool hv = ((unsigned)hh < (unsigned)H_);

        // row[j]: input float at (hh, w0 + j - 1), j = 0..5 (zero outside)
        float4 v = make_float4(0.f, 0.f, 0.f, 0.f);
        float left = 0.f, right = 0.f;
        if (hv) {
            const float* rp = xp + hh * W_;
            v = *reinterpret_cast<const float4*>(rp);
            if (w4 > 0)       left  = rp[-1];
            if (w4 < W4_ - 1) right = rp[4];
        }
        float r0 = left, r1 = v.x, r2 = v.y, r3 = v.z, r4 = v.w, r5 = right;

        float* o = op + (long)(dy * 3) * PLANE_;
        __stcs(reinterpret_cast<float4*>(o),
               make_float4(r0, r1, r2, r3));
        __stcs(reinterpret_cast<float4*>(o + PLANE_),
               make_float4(r1, r2, r3, r4));
        __stcs(reinterpret_cast<float4*>(o + 2 * PLANE_),
               make_float4(r2, r3, r4, r5));
    }
}

extern "C" void kernel_launch(void* const* d_in, const int* in_sizes, int n_in,
                              void* d_out, int out_size)
{
    const float* x = (const float*)d_in[0];
    float* out = (float*)d_out;
    const int threads = 512;
    const int blocks = TOTAL_THREADS_ / threads;  // 3136, exact
    shift_kernel<<<blocks, threads>>>(x, out);
}